// round 11
// baseline (speedup 1.0000x reference)
#include <cuda_runtime.h>

// RotationPerturbationLayer == bilinear sampling with zero padding.
//
// R10: clean coarsening test — 2 pixels/thread at CONSTANT 128 CTAs
// (128 blocks x 128 threads; R6's failure came from collapsing to 32 CTAs,
// not from coarsening itself). Per thread: one theta load + one __sincosf
// amortized over 2 adjacent x-pixels (sx steps by +cos, sy by -sin), all
// 24 tap loads issuable in one batched round trip, stores as 3x STG.64.

#define BB 8
#define CC 3
#define HH 64
#define WW 64
#define NN (HH * WW)   // 4096

__global__ __launch_bounds__(128, 1)
void rotation_bilinear2_kernel(const float* __restrict__ theta,
                               const float* __restrict__ image,
                               float* __restrict__ out)
{
    const int idx = blockIdx.x * blockDim.x + threadIdx.x;  // 0 .. B*N/2-1
    const int b  = idx >> 11;          // / (NN/2)
    const int n2 = idx & 2047;
    const int y  = n2 >> 5;            // / (WW/2)
    const int x  = (n2 & 31) << 1;     // even starting x

    const float t = __ldg(theta + b);
    float st, ct;
    __sincosf(t, &st, &ct);

    const float c_x = (WW - 1) * 0.5f;
    const float c_y = (HH - 1) * 0.5f;
    const float xr = (float)x - c_x;
    const float yr = (float)y - c_y;

    const float sxA = fmaf(ct, xr, fmaf(st, yr, c_x));
    const float syA = fmaf(-st, xr, fmaf(ct, yr, c_y));
    const float sxB = sxA + ct;        // pixel x+1
    const float syB = syA - st;

    const float* img1 = image + NN;
    const float* img2 = image + 2 * NN;

    float a0 = 0.0f, a1 = 0.0f, a2 = 0.0f;   // pixel A accums
    float b0 = 0.0f, b1 = 0.0f, b2 = 0.0f;   // pixel B accums

    // ---- pixel A ----
    {
        const int x0 = __float2int_rd(sxA);
        const int y0 = __float2int_rd(syA);
        const int x1 = x0 + 1;
        const int y1 = y0 + 1;
        const float ax = sxA - (float)x0;
        const float ay = syA - (float)y0;
        const float bx = 1.0f - ax;
        const float by = 1.0f - ay;
        const bool vx0 = (unsigned)x0 < (unsigned)WW;
        const bool vx1 = (unsigned)x1 < (unsigned)WW;

        if ((unsigned)y0 < (unsigned)HH) {
            const int row = y0 * WW;
            if (vx0) {
                const float w = by * bx; const int p = row + x0;
                a0 = fmaf(w, __ldg(image + p), a0);
                a1 = fmaf(w, __ldg(img1 + p),  a1);
                a2 = fmaf(w, __ldg(img2 + p),  a2);
            }
            if (vx1) {
                const float w = by * ax; const int p = row + x1;
                a0 = fmaf(w, __ldg(image + p), a0);
                a1 = fmaf(w, __ldg(img1 + p),  a1);
                a2 = fmaf(w, __ldg(img2 + p),  a2);
            }
        }
        if ((unsigned)y1 < (unsigned)HH) {
            const int row = y1 * WW;
            if (vx0) {
                const float w = ay * bx; const int p = row + x0;
                a0 = fmaf(w, __ldg(image + p), a0);
                a1 = fmaf(w, __ldg(img1 + p),  a1);
                a2 = fmaf(w, __ldg(img2 + p),  a2);
            }
            if (vx1) {
                const float w = ay * ax; const int p = row + x1;
                a0 = fmaf(w, __ldg(image + p), a0);
                a1 = fmaf(w, __ldg(img1 + p),  a1);
                a2 = fmaf(w, __ldg(img2 + p),  a2);
            }
        }
    }

    // ---- pixel B ----
    {
        const int x0 = __float2int_rd(sxB);
        const int y0 = __float2int_rd(syB);
        const int x1 = x0 + 1;
        const int y1 = y0 + 1;
        const float ax = sxB - (float)x0;
        const float ay = syB - (float)y0;
        const float bx = 1.0f - ax;
        const float by = 1.0f - ay;
        const bool vx0 = (unsigned)x0 < (unsigned)WW;
        const bool vx1 = (unsigned)x1 < (unsigned)WW;

        if ((unsigned)y0 < (unsigned)HH) {
            const int row = y0 * WW;
            if (vx0) {
                const float w = by * bx; const int p = row + x0;
                b0 = fmaf(w, __ldg(image + p), b0);
                b1 = fmaf(w, __ldg(img1 + p),  b1);
                b2 = fmaf(w, __ldg(img2 + p),  b2);
            }
            if (vx1) {
                const float w = by * ax; const int p = row + x1;
                b0 = fmaf(w, __ldg(image + p), b0);
                b1 = fmaf(w, __ldg(img1 + p),  b1);
                b2 = fmaf(w, __ldg(img2 + p),  b2);
            }
        }
        if ((unsigned)y1 < (unsigned)HH) {
            const int row = y1 * WW;
            if (vx0) {
                const float w = ay * bx; const int p = row + x0;
                b0 = fmaf(w, __ldg(image + p), b0);
                b1 = fmaf(w, __ldg(img1 + p),  b1);
                b2 = fmaf(w, __ldg(img2 + p),  b2);
            }
            if (vx1) {
                const float w = ay * ax; const int p = row + x1;
                b0 = fmaf(w, __ldg(image + p), b0);
                b1 = fmaf(w, __ldg(img1 + p),  b1);
                b2 = fmaf(w, __ldg(img2 + p),  b2);
            }
        }
    }

    // out [B, C, H, W]; adjacent-x pair -> 3x STG.64 (8B-aligned: x even).
    const int n = y * WW + x;
    float2* ob = (float2*)(out + b * (CC * NN) + n);
    ob[0]          = make_float2(a0, b0);
    ob[NN / 2]     = make_float2(a1, b1);
    ob[NN]         = make_float2(a2, b2);
}

extern "C" void kernel_launch(void* const* d_in, const int* in_sizes, int n_in,
                              void* d_out, int out_size)
{
    const float* theta = (const float*)d_in[0];  // [B,1] = 8 floats
    const float* image = (const float*)d_in[1];  // [C,H,W] = 12288 floats
    float* out = (float*)d_out;                  // [B,C,H,W] = 98304 floats

    // 16384 threads = 128 blocks x 128 -> same CTA count/spread as champion.
    rotation_bilinear2_kernel<<<128, 128>>>(theta, image, out);
}

// round 14
// speedup vs baseline: 1.0048x; 1.0048x over previous
#include <cuda_runtime.h>

// RotationPerturbationLayer == bilinear sampling with zero padding (the dense
// [B,N,N] tent-weight einsum has <=4 nonzero taps per output coordinate;
// taps outside [0,W)x[0,H) contribute zero).
//
// R13 == R11/R12 resubmit (both hit GB300 container-acquisition failures,
// never ran). Kernel body identical to the R9 champion (1 pixel/thread,
// nested per-tap ifs, 26 regs, chain-trimmed). Only the grid shape changes:
// 256 CTAs x 128 threads instead of 128 x 256 — same 32768 threads, but all
// 148 SMs get work (a 128-CTA launch leaves 20 SMs idle) and each CTA runs
// 1 warp per SMSP instead of 2, shrinking the per-SM tail.

#define BB 8
#define CC 3
#define HH 64
#define WW 64
#define NN (HH * WW)   // 4096

__global__ __launch_bounds__(128, 1)
void rotation_bilinear_kernel(const float* __restrict__ theta,
                              const float* __restrict__ image,
                              float* __restrict__ out)
{
    const int idx = blockIdx.x * blockDim.x + threadIdx.x;  // 0 .. B*N-1
    const int b = idx >> 12;        // / NN
    const int n = idx & (NN - 1);   // % NN
    const int y = n >> 6;           // / WW
    const int x = n & (WW - 1);     // % WW

    const float t = __ldg(theta + b);   // 8 distinct values, L2-broadcast
    float st, ct;
    __sincosf(t, &st, &ct);

    const float c_x = (WW - 1) * 0.5f;
    const float c_y = (HH - 1) * 0.5f;
    const float xr = (float)x - c_x;
    const float yr = (float)y - c_y;

    const float sx = fmaf(ct, xr, fmaf(st, yr, c_x));
    const float sy = fmaf(-st, xr, fmaf(ct, yr, c_y));

    const int x0 = __float2int_rd(sx);
    const int y0 = __float2int_rd(sy);
    const int x1 = x0 + 1;
    const int y1 = y0 + 1;

    const float ax = sx - (float)x0;   // tent weight toward x1
    const float ay = sy - (float)y0;
    const float bx = 1.0f - ax;        // tent weight toward x0
    const float by = 1.0f - ay;

    const bool vx0 = (unsigned)x0 < (unsigned)WW;
    const bool vx1 = (unsigned)x1 < (unsigned)WW;
    const bool vy0 = (unsigned)y0 < (unsigned)HH;
    const bool vy1 = (unsigned)y1 < (unsigned)HH;

    const float* img1 = image + NN;
    const float* img2 = image + 2 * NN;

    float acc0 = 0.0f, acc1 = 0.0f, acc2 = 0.0f;

    if (vy0) {
        const int row = y0 * WW;
        if (vx0) {
            const float w = by * bx;
            const int p = row + x0;
            acc0 = fmaf(w, __ldg(image + p), acc0);
            acc1 = fmaf(w, __ldg(img1 + p),  acc1);
            acc2 = fmaf(w, __ldg(img2 + p),  acc2);
        }
        if (vx1) {
            const float w = by * ax;
            const int p = row + x1;
            acc0 = fmaf(w, __ldg(image + p), acc0);
            acc1 = fmaf(w, __ldg(img1 + p),  acc1);
            acc2 = fmaf(w, __ldg(img2 + p),  acc2);
        }
    }
    if (vy1) {
        const int row = y1 * WW;
        if (vx0) {
            const float w = ay * bx;
            const int p = row + x0;
            acc0 = fmaf(w, __ldg(image + p), acc0);
            acc1 = fmaf(w, __ldg(img1 + p),  acc1);
            acc2 = fmaf(w, __ldg(img2 + p),  acc2);
        }
        if (vx1) {
            const float w = ay * ax;
            const int p = row + x1;
            acc0 = fmaf(w, __ldg(image + p), acc0);
            acc1 = fmaf(w, __ldg(img1 + p),  acc1);
            acc2 = fmaf(w, __ldg(img2 + p),  acc2);
        }
    }

    // out [B, C, H, W]: offset = b*3*NN + n = idx + b*2*NN = idx + (b << 13)
    float* ob = out + idx + (b << 13);
    ob[0]      = acc0;
    ob[NN]     = acc1;
    ob[2 * NN] = acc2;
}

extern "C" void kernel_launch(void* const* d_in, const int* in_sizes, int n_in,
                              void* d_out, int out_size)
{
    const float* theta = (const float*)d_in[0];  // [B,1] = 8 floats
    const float* image = (const float*)d_in[1];  // [C,H,W] = 12288 floats
    float* out = (float*)d_out;                  // [B,C,H,W] = 98304 floats

    // 32768 threads as 256 blocks x 128 -> covers all 148 SMs.
    rotation_bilinear_kernel<<<256, 128>>>(theta, image, out);
}